// round 3
// baseline (speedup 1.0000x reference)
#include <cuda_runtime.h>
#include <math.h>

// Problem shape (fixed by the dataset): B=32, L=8192, K=64, 20 amino acids.
#define B_DIM 32
#define L_DIM 8192
#define K_DIM 64
#define THREADS 256
#define WARPS (THREADS / 32)
#define UNROLL 4
#define TILE_ROWS 256            // rows of i per block -> grid 32 x 32

__global__ __launch_bounds__(THREADS, 6)
void hp_pairs_kernel(const int* __restrict__ seq,
                     const float* __restrict__ r,
                     const int* __restrict__ j_idx,
                     const float* __restrict__ h,
                     const float* __restrict__ r_half_raw,
                     const float* __restrict__ tau_hp_raw,
                     const int* __restrict__ max_dist,
                     float* __restrict__ out)
{
    __shared__ float s_hseq[L_DIM];   // h[seq[b, :]] for this batch row (32 KB)

    const int b    = blockIdx.x;      // batch index
    const int tile = blockIdx.y;      // which TILE_ROWS chunk of L
    const int tid  = threadIdx.x;
    const int lane = tid & 31;
    const int warp = tid >> 5;

    // Each lane holds one h-table entry (20 entries <= 32 lanes).
    const float h_lane = h[min(lane, 19)];

    // Stage h[seq[b,:]] into smem: LDG.128 seq -> 4x shfl table lookup -> STS.128.
    // All 8 iterations independent; no table LDS, no bank conflicts.
    {
        const int4* src = (const int4*)(seq + b * L_DIM);
        float4*     dst = (float4*)s_hseq;
        #pragma unroll
        for (int it = 0; it < L_DIM / 4 / THREADS; ++it) {
            int4 s4 = src[tid + it * THREADS];
            float4 v;
            v.x = __shfl_sync(0xffffffffu, h_lane, s4.x);
            v.y = __shfl_sync(0xffffffffu, h_lane, s4.y);
            v.z = __shfl_sync(0xffffffffu, h_lane, s4.z);
            v.w = __shfl_sync(0xffffffffu, h_lane, s4.w);
            dst[tid + it * THREADS] = v;
        }
    }

    // Scalars (broadcast loads; L2 hits).
    const float md     = (float)(*max_dist);
    const float r_peak = log1pf(expf(*r_half_raw));
    const float sigma  = log1pf(expf(*tau_hp_raw)) + 0.1f;
    // g = exp(-d^2/(2 sigma^2)) = 2^( d^2 * (-log2e / (2 sigma^2)) )
    const float nscale = -1.44269504088896340736f / (2.0f * sigma * sigma);
    const float thresh = md - 1e-4f;

    __syncthreads();

    const int half = lane >> 4;       // which of the warp's 2 rows
    const int l15  = lane & 15;       // k-chunk within row (4 floats each)
    const int row0 = tile * TILE_ROWS;
    const int rbase = row0 + warp * 2 + half;   // this thread's first row

    // Single base pointer per array; all unrolled loads use immediate offsets.
    const float* rp = r     + (((size_t)b * L_DIM + rbase) * K_DIM) + l15 * 4;
    const int*   jp = j_idx + (((size_t)b * L_DIM + rbase) * K_DIM) + l15 * 4;
    float*       ob = out   + (size_t)b * L_DIM;

    #pragma unroll
    for (int mi = 0; mi < TILE_ROWS / (WARPS * UNROLL * 2); ++mi) {
        // ---- batched load phase: 8 independent LDG.128 in flight ----
        float4 rv[UNROLL];
        int4   jv[UNROLL];
        #pragma unroll
        for (int u = 0; u < UNROLL; ++u)
            rv[u] = *(const float4*)(rp + (size_t)u * (WARPS * 2 * K_DIM));
        #pragma unroll
        for (int u = 0; u < UNROLL; ++u)
            jv[u] = *(const int4*)(jp + (size_t)u * (WARPS * 2 * K_DIM));

        // ---- compute phase ----
        #pragma unroll
        for (int u = 0; u < UNROLL; ++u) {
            const int j0 = min(max(jv[u].x, 0), L_DIM - 1);
            const int j1 = min(max(jv[u].y, 0), L_DIM - 1);
            const int j2 = min(max(jv[u].z, 0), L_DIM - 1);
            const int j3 = min(max(jv[u].w, 0), L_DIM - 1);
            const float hj0 = s_hseq[j0];
            const float hj1 = s_hseq[j1];
            const float hj2 = s_hseq[j2];
            const float hj3 = s_hseq[j3];

            const float d0 = fminf(rv[u].x, md) - r_peak;
            const float d1 = fminf(rv[u].y, md) - r_peak;
            const float d2 = fminf(rv[u].z, md) - r_peak;
            const float d3 = fminf(rv[u].w, md) - r_peak;

            float g0, g1, g2, g3;
            asm("ex2.approx.ftz.f32 %0, %1;" : "=f"(g0) : "f"(d0 * d0 * nscale));
            asm("ex2.approx.ftz.f32 %0, %1;" : "=f"(g1) : "f"(d1 * d1 * nscale));
            asm("ex2.approx.ftz.f32 %0, %1;" : "=f"(g2) : "f"(d2 * d2 * nscale));
            asm("ex2.approx.ftz.f32 %0, %1;" : "=f"(g3) : "f"(d3 * d3 * nscale));

            g0 = (rv[u].x < thresh) ? g0 : 0.0f;
            g1 = (rv[u].y < thresh) ? g1 : 0.0f;
            g2 = (rv[u].z < thresh) ? g2 : 0.0f;
            g3 = (rv[u].w < thresh) ? g3 : 0.0f;

            float acc = fmaf(hj0, g0, hj1 * g1) + fmaf(hj2, g2, hj3 * g3);

            // reduce over the 16 lanes holding this row
            #pragma unroll
            for (int off = 8; off; off >>= 1)
                acc += __shfl_xor_sync(0xffffffffu, acc, off);

            const int row = rbase + mi * (WARPS * UNROLL * 2) + u * (WARPS * 2);
            if (l15 == 0)
                ob[row] = s_hseq[row] * acc;
        }

        rp += (size_t)(WARPS * UNROLL * 2) * K_DIM;
        jp += (size_t)(WARPS * UNROLL * 2) * K_DIM;
    }
}

extern "C" void kernel_launch(void* const* d_in, const int* in_sizes, int n_in,
                              void* d_out, int out_size)
{
    // metadata order: seq, r, j_idx, h, r_half_raw, tau_hp_raw, max_dist
    const int*   seq        = (const int*)d_in[0];
    const float* r          = (const float*)d_in[1];
    const int*   j_idx      = (const int*)d_in[2];
    const float* h          = (const float*)d_in[3];
    const float* r_half_raw = (const float*)d_in[4];
    const float* tau_hp_raw = (const float*)d_in[5];
    const int*   max_dist   = (const int*)d_in[6];
    float*       out        = (float*)d_out;

    dim3 grid(B_DIM, L_DIM / TILE_ROWS);   // 32 x 32 = 1024 blocks
    hp_pairs_kernel<<<grid, THREADS>>>(seq, r, j_idx, h,
                                       r_half_raw, tau_hp_raw, max_dist, out);
}

// round 5
// speedup vs baseline: 1.2696x; 1.2696x over previous
#include <cuda_runtime.h>
#include <math.h>

// Problem shape (fixed by dataset): B=32, L=8192, K=64, 20 amino acids.
#define B_DIM 32
#define L_DIM 8192
#define K_DIM 64
#define THREADS 256
#define WARPS (THREADS / 32)
#define UNROLL 2
#define ROWS_PER_U  (WARPS * 4)            // 32 rows per unroll step
#define ROWS_PER_MI (ROWS_PER_U * UNROLL)  // 64 rows per macro-iter
#define TILE_ROWS 128                      // grid = 32 x 64 = 2048 blocks

__global__ __launch_bounds__(THREADS, 5)
void hp_pairs_kernel(const int* __restrict__ seq,
                     const float* __restrict__ r,
                     const int* __restrict__ j_idx,
                     const float* __restrict__ h,
                     const float* __restrict__ r_half_raw,
                     const float* __restrict__ tau_hp_raw,
                     const int* __restrict__ max_dist,
                     float* __restrict__ out)
{
    __shared__ float s_hseq[L_DIM];   // h[seq[b, :]] for this batch row (32 KB)

    const int b    = blockIdx.x;
    const int tile = blockIdx.y;
    const int tid  = threadIdx.x;
    const int lane = tid & 31;
    const int warp = tid >> 5;

    // Each lane holds one h-table entry (20 entries <= 32 lanes).
    const float h_lane = h[min(lane, 19)];

    // Stage h[seq[b,:]] into smem: LDG.128 seq -> 4x shfl lookup -> STS.128.
    {
        const int4* src = (const int4*)(seq + b * L_DIM);
        float4*     dst = (float4*)s_hseq;
        #pragma unroll
        for (int it = 0; it < L_DIM / 4 / THREADS; ++it) {
            int4 s4 = src[tid + it * THREADS];
            float4 v;
            v.x = __shfl_sync(0xffffffffu, h_lane, s4.x);
            v.y = __shfl_sync(0xffffffffu, h_lane, s4.y);
            v.z = __shfl_sync(0xffffffffu, h_lane, s4.z);
            v.w = __shfl_sync(0xffffffffu, h_lane, s4.w);
            dst[tid + it * THREADS] = v;
        }
    }

    // Scalars (broadcast loads; L2 hits).
    const float md     = (float)(*max_dist);
    const float r_peak = log1pf(expf(*r_half_raw));
    const float sigma  = log1pf(expf(*tau_hp_raw)) + 0.1f;
    // g = exp(-d^2/(2 sigma^2)) = 2^( d^2 * (-log2e / (2 sigma^2)) )
    const float nscale = -1.44269504088896340736f / (2.0f * sigma * sigma);
    const float thresh = md - 1e-4f;

    __syncthreads();

    // Mapping: 8 lanes per row, 4 rows per warp.
    const int l8   = lane & 7;        // k-chunk lane within row
    const int rgrp = lane >> 3;       // row within warp's group of 4
    const int rowbase = tile * TILE_ROWS + warp * 4 + rgrp;

    const float* rb = r     + ((size_t)b * L_DIM) * K_DIM;
    const int*   jb = j_idx + ((size_t)b * L_DIM) * K_DIM;
    float*       ob = out   + (size_t)b * L_DIM;

    #pragma unroll
    for (int mi = 0; mi < TILE_ROWS / ROWS_PER_MI; ++mi) {
        // ---- batched load phase: 8 independent LDG.128 (4 KB/warp) ----
        // thread covers k = l8*4..+4 and l8*4+32..+4 of its row.
        float4 ra[UNROLL][2];
        int4   ja[UNROLL][2];
        int    rowA[UNROLL];
        #pragma unroll
        for (int u = 0; u < UNROLL; ++u) {
            const int row = rowbase + mi * ROWS_PER_MI + u * ROWS_PER_U;
            rowA[u] = row;
            const float* rp = rb + (size_t)row * K_DIM + l8 * 4;
            const int*   jp = jb + (size_t)row * K_DIM + l8 * 4;
            ra[u][0] = __ldcs((const float4*)rp);
            ra[u][1] = __ldcs((const float4*)(rp + 32));
            ja[u][0] = __ldcs((const int4*)jp);
            ja[u][1] = __ldcs((const int4*)(jp + 32));
        }

        // ---- compute phase ----
        #pragma unroll
        for (int u = 0; u < UNROLL; ++u) {
            float acc = 0.0f;
            #pragma unroll
            for (int p = 0; p < 2; ++p) {
                const float4 rv = ra[u][p];
                const int4   jv = ja[u][p];
                const int j0 = min(max(jv.x, 0), L_DIM - 1);
                const int j1 = min(max(jv.y, 0), L_DIM - 1);
                const int j2 = min(max(jv.z, 0), L_DIM - 1);
                const int j3 = min(max(jv.w, 0), L_DIM - 1);
                const float hj0 = s_hseq[j0];
                const float hj1 = s_hseq[j1];
                const float hj2 = s_hseq[j2];
                const float hj3 = s_hseq[j3];

                const float d0 = fminf(rv.x, md) - r_peak;
                const float d1 = fminf(rv.y, md) - r_peak;
                const float d2 = fminf(rv.z, md) - r_peak;
                const float d3 = fminf(rv.w, md) - r_peak;

                float g0, g1, g2, g3;
                asm("ex2.approx.ftz.f32 %0, %1;" : "=f"(g0) : "f"(d0 * d0 * nscale));
                asm("ex2.approx.ftz.f32 %0, %1;" : "=f"(g1) : "f"(d1 * d1 * nscale));
                asm("ex2.approx.ftz.f32 %0, %1;" : "=f"(g2) : "f"(d2 * d2 * nscale));
                asm("ex2.approx.ftz.f32 %0, %1;" : "=f"(g3) : "f"(d3 * d3 * nscale));

                g0 = (rv.x < thresh) ? g0 : 0.0f;
                g1 = (rv.y < thresh) ? g1 : 0.0f;
                g2 = (rv.z < thresh) ? g2 : 0.0f;
                g3 = (rv.w < thresh) ? g3 : 0.0f;

                acc += fmaf(hj0, g0, hj1 * g1) + fmaf(hj2, g2, hj3 * g3);
            }

            // reduce over the 8 lanes holding this row (3 chained shfl)
            acc += __shfl_xor_sync(0xffffffffu, acc, 4);
            acc += __shfl_xor_sync(0xffffffffu, acc, 2);
            acc += __shfl_xor_sync(0xffffffffu, acc, 1);

            if (l8 == 0)
                ob[rowA[u]] = s_hseq[rowA[u]] * acc;
        }
    }
}

extern "C" void kernel_launch(void* const* d_in, const int* in_sizes, int n_in,
                              void* d_out, int out_size)
{
    // metadata order: seq, r, j_idx, h, r_half_raw, tau_hp_raw, max_dist
    const int*   seq        = (const int*)d_in[0];
    const float* r          = (const float*)d_in[1];
    const int*   j_idx      = (const int*)d_in[2];
    const float* h          = (const float*)d_in[3];
    const float* r_half_raw = (const float*)d_in[4];
    const float* tau_hp_raw = (const float*)d_in[5];
    const int*   max_dist   = (const int*)d_in[6];
    float*       out        = (float*)d_out;

    dim3 grid(B_DIM, L_DIM / TILE_ROWS);   // 32 x 64 = 2048 blocks
    hp_pairs_kernel<<<grid, THREADS>>>(seq, r, j_idx, h,
                                       r_half_raw, tau_hp_raw, max_dist, out);
}